// round 1
// baseline (speedup 1.0000x reference)
#include <cuda_runtime.h>

// Problem constants (fixed by the dataset): B=32, N=64, L=128, D=256.
// All sizes are derived at launch time from in_sizes/out_size, but the static
// scratch below is sized for this shape with headroom.

#define T_CHUNK 128          // t-positions handled per block in k_main

// Static device scratch (allocation-free rule: __device__ globals only).
__device__ int   g_off[4096];          // NB exclusive offsets (NB=2048 actual)
__device__ float g_lenf[128];          // per-batch total length (B=32 actual)
__device__ int   g_map[524288];        // B*MAX_LEN token map (262144 actual)
__device__ float g_partial[1048576];   // B * nchunks * D partials (32*64*256=524288 actual)

// ---------------------------------------------------------------------------
// Kernel A: per-batch exclusive scan of lengths.  grid = B, block = N threads.
__global__ void k_scan(const int* __restrict__ lengths, int N,
                       float* __restrict__ len_out)
{
    __shared__ int s[1024];
    int b = blockIdx.x;
    int n = threadIdx.x;
    int len = lengths[b * N + n];
    s[n] = len;
    __syncthreads();
    // simple Hillis-Steele inclusive scan (N <= 1024; actual 64)
    for (int st = 1; st < N; st <<= 1) {
        int v = (n >= st) ? s[n - st] : 0;
        __syncthreads();
        s[n] += v;
        __syncthreads();
    }
    g_off[b * N + n] = s[n] - len;
    if (n == N - 1) {
        float tot = (float)s[n];
        len_out[b] = tot;
        g_lenf[b]  = tot;
    }
}

// ---------------------------------------------------------------------------
// Kernel B: init map = -1 and src_out = 1.0 for all B*MAX_LEN slots.
__global__ void k_init(float* __restrict__ src_out, int total)
{
    int i = blockIdx.x * blockDim.x + threadIdx.x;
    if (i < total) {
        g_map[i]   = -1;
        src_out[i] = 1.0f;
    }
}

// ---------------------------------------------------------------------------
// Kernel C: scatter valid tokens into the map; gather src through `recover`.
// idx = p*NB + nb  (the global token index into memory_bank's [L, NB, .] order)
__global__ void k_scatter(const float* __restrict__ src,
                          const int* __restrict__ lengths,
                          const int* __restrict__ recover,
                          int NB, int N, int MAX_LEN, int B, int total,
                          float* __restrict__ src_out)
{
    int idx = blockIdx.x * blockDim.x + threadIdx.x;
    if (idx >= total) return;
    int nb = idx % NB;
    int p  = idx / NB;
    int len = lengths[nb];
    if (p < len) {
        int b = nb / N;
        int t = g_off[nb] + p;
        g_map[b * MAX_LEN + t] = idx;                 // idx == p*NB + nb
        src_out[t * B + b] = src[p * NB + recover[nb]];
    }
}

// ---------------------------------------------------------------------------
// Kernel D: main streaming pass.
// grid = (MAX_LEN / T_CHUNK, B), block = 256 threads.
// Thread layout: d4 = tid & 63 (float4 lane over D=256), ts = tid >> 6 (t sub).
// Each block writes one [T_CHUNK, D] slab of mb_out and emits one deterministic
// partial sum vector of length D into g_partial.
__global__ void k_main(const float4* __restrict__ mb,
                       float4* __restrict__ mb_out,
                       int B, int Dv /* D/4 */, int MAX_LEN, int nchunks)
{
    int b     = blockIdx.y;
    int chunk = blockIdx.x;
    int t0    = chunk * T_CHUNK;
    int d4    = threadIdx.x & 63;
    int ts    = threadIdx.x >> 6;

    const int* __restrict__ mrow = g_map + b * MAX_LEN + t0;

    float4 acc = make_float4(0.f, 0.f, 0.f, 0.f);

    #pragma unroll 4
    for (int tt = ts; tt < T_CHUNK; tt += 4) {
        int tok = mrow[tt];                     // warp-uniform broadcast
        float4 v = make_float4(0.f, 0.f, 0.f, 0.f);
        if (tok >= 0)
            v = mb[(long)tok * Dv + d4];        // coalesced 1KB row read
        int t = t0 + tt;
        mb_out[((long)(t * B + b)) * Dv + d4] = v;   // coalesced 1KB row write
        acc.x += v.x; acc.y += v.y; acc.z += v.z; acc.w += v.w;
    }

    // deterministic block reduction over the 4 t-subgroups
    __shared__ float4 sred[256];
    sred[threadIdx.x] = acc;
    __syncthreads();
    if (ts == 0) {
        float4 a0 = sred[d4];
        float4 a1 = sred[64  + d4];
        float4 a2 = sred[128 + d4];
        float4 a3 = sred[192 + d4];
        float4 tot;
        tot.x = (a0.x + a1.x) + (a2.x + a3.x);
        tot.y = (a0.y + a1.y) + (a2.y + a3.y);
        tot.z = (a0.z + a1.z) + (a2.z + a3.z);
        tot.w = (a0.w + a1.w) + (a2.w + a3.w);
        // partial layout: [(b*nchunks + chunk) * D + d]
        float4* pp = (float4*)g_partial;
        pp[(long)(b * nchunks + chunk) * Dv + d4] = tot;
    }
}

// ---------------------------------------------------------------------------
// Kernel E: reduce chunk partials -> encoder_hidden = sum / lengths_out.
__global__ void k_final(float* __restrict__ hid_out, int B, int D, int nch)
{
    int i = blockIdx.x * blockDim.x + threadIdx.x;
    if (i >= B * D) return;
    int b = i / D;
    int d = i - b * D;
    const float* p = g_partial + (long)(b * nch) * D + d;
    float s = 0.f;
    for (int c = 0; c < nch; c++)
        s += p[(long)c * D];
    hid_out[i] = s / g_lenf[b];
}

// ---------------------------------------------------------------------------
extern "C" void kernel_launch(void* const* d_in, const int* in_sizes, int n_in,
                              void* d_out, int out_size)
{
    const float* src     = (const float*)d_in[0];   // [L, NB, 1]
    const float* mb      = (const float*)d_in[1];   // [L, NB, D]
    const int*   lengths = (const int*)  d_in[2];   // [NB]
    const int*   recover = (const int*)  d_in[3];   // [NB]

    int NB = in_sizes[2];
    int L  = in_sizes[0] / NB;
    int D  = in_sizes[1] / in_sizes[0];

    // out_size = NB*L*(1+D) + B*(D+1)  ->  solve for B, then N = NB/B.
    long rem = (long)out_size - (long)NB * L * (1 + D);
    int B = (int)(rem / (D + 1));
    int N = NB / B;
    int MAX_LEN = N * L;

    float* out      = (float*)d_out;
    float* src_out  = out;                                   // [MAX_LEN, B, 1]
    float* mb_out   = out + (long)MAX_LEN * B;               // [MAX_LEN, B, D]
    float* hid_out  = mb_out + (long)MAX_LEN * B * D;        // [1, B, D]
    float* len_out  = hid_out + (long)B * D;                 // [B]

    // A: scan
    k_scan<<<B, N>>>(lengths, N, len_out);

    // B: init map/src_out
    int totalBM = B * MAX_LEN;
    k_init<<<(totalBM + 255) / 256, 256>>>(src_out, totalBM);

    // C: scatter valid tokens
    int totalTok = NB * L;
    k_scatter<<<(totalTok + 255) / 256, 256>>>(src, lengths, recover,
                                               NB, N, MAX_LEN, B, totalTok,
                                               src_out);

    // D: main streaming gather + partial sums
    int nchunks = MAX_LEN / T_CHUNK;
    dim3 gridD(nchunks, B);
    k_main<<<gridD, 256>>>((const float4*)mb, (float4*)mb_out,
                           B, D / 4, MAX_LEN, nchunks);

    // E: finalize encoder hidden
    k_final<<<(B * D + 255) / 256, 256>>>(hid_out, B, D, nchunks);
}

// round 2
// speedup vs baseline: 1.1134x; 1.1134x over previous
#include <cuda_runtime.h>

// Problem shape (dataset-fixed): B=32, N=64, L=128, D=256, NB=2048, MAX_LEN=8192.
// All sizes derived at launch; static scratch sized with headroom.

#define T_CHUNK 128          // t-positions per k_main block

// Static device scratch (allocation-free rule).
__device__ int   g_off[8448];          // B*(N+1) offsets; off[N]=total  (32*65 actual)
__device__ float g_lenf[128];          // per-batch total length (B=32 actual)
__device__ float g_partial[1048576];   // B * nchunks * D partials (32*64*256 actual)

// ---------------------------------------------------------------------------
// Kernel A: per-batch inclusive scan of lengths -> exclusive offsets + sentinel.
// grid = B, block = N threads.
__global__ void k_scan(const int* __restrict__ lengths, int N,
                       float* __restrict__ len_out)
{
    __shared__ int s[1024];
    int b = blockIdx.x;
    int n = threadIdx.x;
    int len = lengths[b * N + n];
    s[n] = len;
    __syncthreads();
    for (int st = 1; st < N; st <<= 1) {
        int v = (n >= st) ? s[n - st] : 0;
        __syncthreads();
        s[n] += v;
        __syncthreads();
    }
    g_off[b * (N + 1) + n] = s[n] - len;           // exclusive
    if (n == N - 1) {
        g_off[b * (N + 1) + N] = s[n];             // sentinel: total
        float tot = (float)s[n];
        len_out[b] = tot;
        g_lenf[b]  = tot;
    }
}

// ---------------------------------------------------------------------------
// Kernel B: fused main pass.
// grid = (MAX_LEN/T_CHUNK, B), block = 256 threads.
//   d4 = tid & 63 : float4 lane over D=256
//   ts = tid >> 6 : t sub-stride (4 subgroups)
// Per block: resolve t -> (node n, pos p) via smem offset table (binary search
// + monotone advance), stream mb rows, write src_out, emit partial sums.
__global__ void __launch_bounds__(256)
k_main(const float4* __restrict__ mb,
       float4* __restrict__ mb_out,
       const float* __restrict__ src,
       const int* __restrict__ recover,
       float* __restrict__ src_out,
       int B, int N, int NB, int Dv, int MAX_LEN, int nchunks)
{
    __shared__ int soff[1056];     // N+1 entries (65 actual)

    int b     = blockIdx.y;
    int chunk = blockIdx.x;
    int t0    = chunk * T_CHUNK;
    int tid   = threadIdx.x;

    for (int i = tid; i <= N; i += blockDim.x)
        soff[i] = g_off[b * (N + 1) + i];
    __syncthreads();

    int total = soff[N];

    // --- src_out for this chunk (threads 0..T_CHUNK-1, one t each) ---
    if (tid < T_CHUNK) {
        int t = t0 + tid;
        float val = 1.0f;
        if (t < total) {
            int lo = 0, hi = N - 1;
            while (lo < hi) {                       // largest n: soff[n] <= t
                int mid = (lo + hi + 1) >> 1;
                if (soff[mid] <= t) lo = mid; else hi = mid - 1;
            }
            int p = t - soff[lo];
            val = src[p * NB + recover[b * N + lo]];
        }
        src_out[t * B + b] = val;
    }

    // --- main stream: mb gather -> mb_out + partial sum ---
    int d4 = tid & 63;
    int ts = tid >> 6;

    // initial node index for first t this thread handles
    int n = 0;
    {
        int t = t0 + ts;
        int lo = 0, hi = N - 1;
        while (lo < hi) {
            int mid = (lo + hi + 1) >> 1;
            if (soff[mid] <= t) lo = mid; else hi = mid - 1;
        }
        n = lo;
    }

    int row_base = b * N;        // nb_global base
    float4 acc = make_float4(0.f, 0.f, 0.f, 0.f);

    #pragma unroll 4
    for (int tt = ts; tt < T_CHUNK; tt += 4) {
        int t = t0 + tt;
        float4 v = make_float4(0.f, 0.f, 0.f, 0.f);
        if (t < total) {
            while (n + 1 < N && soff[n + 1] <= t) n++;   // monotone advance
            int p   = t - soff[n];
            long tok = (long)(p * NB + row_base + n);
            v = __ldcs(&mb[tok * Dv + d4]);              // streaming 1KB row read
        }
        __stcs(&mb_out[((long)(t * B + b)) * Dv + d4], v);  // streaming write
        acc.x += v.x; acc.y += v.y; acc.z += v.z; acc.w += v.w;
    }

    // deterministic block reduction over the 4 t-subgroups
    __shared__ float4 sred[256];
    sred[tid] = acc;
    __syncthreads();
    if (ts == 0) {
        float4 a0 = sred[d4];
        float4 a1 = sred[64  + d4];
        float4 a2 = sred[128 + d4];
        float4 a3 = sred[192 + d4];
        float4 tot;
        tot.x = (a0.x + a1.x) + (a2.x + a3.x);
        tot.y = (a0.y + a1.y) + (a2.y + a3.y);
        tot.z = (a0.z + a1.z) + (a2.z + a3.z);
        tot.w = (a0.w + a1.w) + (a2.w + a3.w);
        float4* pp = (float4*)g_partial;
        pp[(long)(b * nchunks + chunk) * Dv + d4] = tot;
    }
}

// ---------------------------------------------------------------------------
// Kernel C: reduce chunk partials -> encoder_hidden = sum / lengths_out.
__global__ void k_final(float* __restrict__ hid_out, int B, int D, int nch)
{
    int i = blockIdx.x * blockDim.x + threadIdx.x;
    if (i >= B * D) return;
    int b = i / D;
    int d = i - b * D;
    const float* p = g_partial + (long)(b * nch) * D + d;
    float s = 0.f;
    #pragma unroll 8
    for (int c = 0; c < nch; c++)
        s += p[(long)c * D];
    hid_out[i] = s / g_lenf[b];
}

// ---------------------------------------------------------------------------
extern "C" void kernel_launch(void* const* d_in, const int* in_sizes, int n_in,
                              void* d_out, int out_size)
{
    const float* src     = (const float*)d_in[0];   // [L, NB, 1]
    const float* mb      = (const float*)d_in[1];   // [L, NB, D]
    const int*   lengths = (const int*)  d_in[2];   // [NB]
    const int*   recover = (const int*)  d_in[3];   // [NB]

    int NB = in_sizes[2];
    int L  = in_sizes[0] / NB;
    int D  = in_sizes[1] / in_sizes[0];

    // out_size = NB*L*(1+D) + B*(D+1)  ->  solve for B.
    long rem = (long)out_size - (long)NB * L * (1 + D);
    int B = (int)(rem / (D + 1));
    int N = NB / B;
    int MAX_LEN = N * L;

    float* out      = (float*)d_out;
    float* src_out  = out;                                   // [MAX_LEN, B, 1]
    float* mb_out   = out + (long)MAX_LEN * B;               // [MAX_LEN, B, D]
    float* hid_out  = mb_out + (long)MAX_LEN * B * D;        // [1, B, D]
    float* len_out  = hid_out + (long)B * D;                 // [B]

    // A: scan
    k_scan<<<B, N>>>(lengths, N, len_out);

    // B: fused main streaming pass
    int nchunks = MAX_LEN / T_CHUNK;
    dim3 gridB(nchunks, B);
    k_main<<<gridB, 256>>>((const float4*)mb, (float4*)mb_out,
                           src, recover, src_out,
                           B, N, NB, D / 4, MAX_LEN, nchunks);

    // C: finalize encoder hidden
    k_final<<<(B * D + 255) / 256, 256>>>(hid_out, B, D, nchunks);
}